// round 9
// baseline (speedup 1.0000x reference)
#include <cuda_runtime.h>
#include <cstdint>

#define PI_F 3.14159265358979323846f
#define LOG2E_F 1.44269504088896340736f

constexpr int C_IN    = 256;
constexpr int HW      = 256 * 256;     // 65536
constexpr int BATCH   = 8;
constexpr int NTHR    = 128;
constexpr int HALF_T  = 64;            // threads per channel-half
constexpr int PPT     = 4;             // pixels per thread in the conv loop
constexpr int PPB     = HALF_T * PPT;  // 256 pixels per block
constexpr int CH_HALF = C_IN / 2;      // 128 channels per half
constexpr int RING_CH = 6;             // ring slots (channels) per half

// ---- fast math helpers (MUFU-based) ----
__device__ __forceinline__ float ex2_(float x) {
    float y; asm("ex2.approx.f32 %0, %1;" : "=f"(y) : "f"(x)); return y;
}
__device__ __forceinline__ float rcp_(float x) {
    float y; asm("rcp.approx.f32 %0, %1;" : "=f"(y) : "f"(x)); return y;
}
__device__ __forceinline__ float rsq_(float x) {
    float y; asm("rsqrt.approx.f32 %0, %1;" : "=f"(y) : "f"(x)); return y;
}
__device__ __forceinline__ float sigmoid_(float x) {
    return rcp_(1.0f + ex2_(-LOG2E_F * x));
}
__device__ __forceinline__ float tanh_(float x) {
    return 1.0f - 2.0f * rcp_(1.0f + ex2_(2.0f * LOG2E_F * x));
}

// ---- cp.async helpers (smem address as precomputed offset) ----
__device__ __forceinline__ void cpa16o_(unsigned saddr, const void* gsrc) {
    asm volatile("cp.async.cg.shared.global [%0], [%1], 16;\n"
                 :: "r"(saddr), "l"(gsrc) : "memory");
}
__device__ __forceinline__ void cpa_commit_() {
    asm volatile("cp.async.commit_group;\n" ::: "memory");
}
__device__ __forceinline__ void cpa_wait2_() {
    asm volatile("cp.async.wait_group 2;\n" ::: "memory");
}
__device__ __forceinline__ void cpa_wait1_() {
    asm volatile("cp.async.wait_group 1;\n" ::: "memory");
}
__device__ __forceinline__ void cpa_wait0_() {
    asm volatile("cp.async.wait_group 0;\n" ::: "memory");
}

// ---- streaming stores (.cs: evict-first, outputs have no reuse) ----
__device__ __forceinline__ void stcs4_(float* p, float a, float b, float c, float d) {
    asm volatile("st.global.cs.v4.f32 [%0], {%1, %2, %3, %4};"
                 :: "l"(p), "f"(a), "f"(b), "f"(c), "f"(d) : "memory");
}
__device__ __forceinline__ void stcs2_(float* p, float a, float b) {
    asm volatile("st.global.cs.v2.f32 [%0], {%1, %2};"
                 :: "l"(p), "f"(a), "f"(b) : "memory");
}

// Consume one channel from ring slot SLOT (compile-time), weights pA/pB/pC[WIDX].
#define CONSUME_CH(SLOT, WIDX) do {                                          \
    const float4 f  = ringH[(SLOT) * HALF_T + lt];                           \
    const float4 wA = pA[WIDX];                                              \
    const float4 wB = pB[WIDX];                                              \
    const float2 wC = pC[WIDX];                                              \
    const float w[10] = {wA.x, wA.y, wA.z, wA.w, wB.x, wB.y, wB.z, wB.w,     \
                         wC.x, wC.y};                                        \
    const float fv[4] = {f.x, f.y, f.z, f.w};                                \
    _Pragma("unroll")                                                        \
    for (int o = 0; o < 10; ++o)                                             \
      _Pragma("unroll")                                                      \
      for (int j = 0; j < 4; ++j)                                            \
        acc[o][j] = fmaf(fv[j], w[o], acc[o][j]);                            \
  } while (0)

// Group body, 6-slot ring, slot period 3, depth 3 groups (wait 2).
// SP = g%3. Consumes slots 2SP,2SP+1 (channels WI,WI+1); then issues group
// g+3 (channels WI+6,WI+7) into the SAME two slots. Safe: each cell is
// self-produced/self-consumed per thread, and the LDS above issues before
// the async write below; data lands >= L2 latency later.
#define GROUP_BODY(SP, WI) {                                                 \
    cpa_wait2_();                                                            \
    CONSUME_CH(2 * (SP),     (WI));                                          \
    CONSUME_CH(2 * (SP) + 1, (WI) + 1);                                      \
    cpa16o_(rbase + (2 * (SP))     * (HALF_T * 16),                          \
            glp_m + (size_t)((WI) + 6) * HW);                                \
    cpa16o_(rbase + (2 * (SP) + 1) * (HALF_T * 16),                          \
            glp_m + (size_t)((WI) + 7) * HW);                                \
    cpa_commit_();                                                           \
  }

__global__ __launch_bounds__(NTHR, 9)
void brdf_fused_kernel(const float* __restrict__ feats,
                       const float* __restrict__ wi,
                       const float* __restrict__ wo,
                       const float* __restrict__ w_normal,
                       const float* __restrict__ w_albedo,
                       const float* __restrict__ w_rough,
                       const float* __restrict__ w_fresnel,
                       float* __restrict__ out_imgs,
                       float* __restrict__ out_data)
{
    // Weights in 3 aligned split arrays: 3 LDS broadcasts per channel. 10 KB.
    __shared__ float4 swA[C_IN];   // n0 n1 n2 a0
    __shared__ float4 swB[C_IN];   // a1 a2 r  f0
    __shared__ float2 swC[C_IN];   // f1 f2
    // Ring: 2 halves x 6 channel slots x 64 threads x 16 B = 12 KB.
    // After the loop it is reused as the 10x256-float merge buffer (10 KB).
    __shared__ __align__(16) float4 ringbuf[2 * RING_CH * HALF_T];

    const int tid = threadIdx.x;
    for (int i = tid; i < C_IN; i += NTHR) {
        swA[i] = make_float4(w_normal[0 * C_IN + i], w_normal[1 * C_IN + i],
                             w_normal[2 * C_IN + i], w_albedo[0 * C_IN + i]);
        swB[i] = make_float4(w_albedo[1 * C_IN + i], w_albedo[2 * C_IN + i],
                             w_rough[i],             w_fresnel[0 * C_IN + i]);
        swC[i] = make_float2(w_fresnel[1 * C_IN + i], w_fresnel[2 * C_IN + i]);
    }
    __syncthreads();

    const int h  = tid >> 6;        // channel-half: 0 or 1
    const int lt = tid & 63;        // lane within half

    const long long blockpix = (long long)blockIdx.x * PPB;
    const int b   = (int)(blockpix / HW);
    const int hwb = (int)(blockpix % HW);

    // This thread's 16B pixel slice in channel (h*128 + 0).
    const float* gl = feats + (size_t)b * C_IN * HW
                    + (size_t)(h * CH_HALF) * HW + hwb + lt * 4;

    float4* ringH = ringbuf + h * (RING_CH * HALF_T);
    const float4* pA = swA + h * CH_HALF;
    const float4* pB = swB + h * CH_HALF;
    const float2* pC = swC + h * CH_HALF;

    // Precomputed smem byte address of this thread's cell in slot 0.
    const unsigned rbase =
        (unsigned)__cvta_generic_to_shared(ringH) + (unsigned)(lt * 16);

    float acc[10][4];
#pragma unroll
    for (int o = 0; o < 10; ++o)
#pragma unroll
        for (int j = 0; j < 4; ++j) acc[o][j] = 0.f;

    // ---- prologue: groups 0,1,2 -> slots 0..5 (3 groups in flight) ----
    cpa16o_(rbase + 0 * (HALF_T * 16), gl);
    cpa16o_(rbase + 1 * (HALF_T * 16), gl + (size_t)HW);
    cpa_commit_();
    cpa16o_(rbase + 2 * (HALF_T * 16), gl + 2 * (size_t)HW);
    cpa16o_(rbase + 3 * (HALF_T * 16), gl + 3 * (size_t)HW);
    cpa_commit_();
    cpa16o_(rbase + 4 * (HALF_T * 16), gl + 4 * (size_t)HW);
    cpa16o_(rbase + 5 * (HALF_T * 16), gl + 5 * (size_t)HW);
    cpa_commit_();

    const float* glp_m = gl;   // base of current 6-channel macro block

    // ---- main loop: 20 macro-iterations x 3 groups = groups 0..59 ----
#pragma unroll 1
    for (int m = 0; m < 20; ++m) {
        GROUP_BODY(0, 0);      // consumes ch +0,+1, issues ch +6,+7
        GROUP_BODY(1, 2);      // consumes ch +2,+3, issues ch +8,+9
        GROUP_BODY(2, 4);      // consumes ch +4,+5, issues ch +10,+11
        pA += 6; pB += 6; pC += 6;
        glp_m += (size_t)6 * HW;
    }

    // ---- tail: groups 60..63 (local channels 120..127) ----
    GROUP_BODY(0, 0);          // g=60: ch 120,121; issues ch 126,127 -> slots 0,1
    cpa_wait2_();              // g=61 landed
    CONSUME_CH(2, 2);          // ch 122
    CONSUME_CH(3, 3);          // ch 123
    cpa_wait1_();              // g=62 landed
    CONSUME_CH(4, 4);          // ch 124
    CONSUME_CH(5, 5);          // ch 125
    cpa_wait0_();              // g=63 landed; ring fully drained
    CONSUME_CH(0, 6);          // ch 126
    CONSUME_CH(1, 7);          // ch 127

    // ---- merge the two channel-halves through smem (ring is dead now) ----
    __syncthreads();

    float* merge = reinterpret_cast<float*>(ringbuf);   // [o][px]: 10 x 256
    if (h == 1) {
#pragma unroll
        for (int o = 0; o < 10; ++o)
            *reinterpret_cast<float4*>(&merge[o * PPB + lt * 4]) =
                make_float4(acc[o][0], acc[o][1], acc[o][2], acc[o][3]);
    }
    __syncthreads();
    if (h == 0) {
#pragma unroll
        for (int o = 0; o < 10; ++o) {
            float4* mp = reinterpret_cast<float4*>(&merge[o * PPB + lt * 4]);
            float4 m = *mp;
            m.x += acc[o][0]; m.y += acc[o][1];
            m.z += acc[o][2]; m.w += acc[o][3];
            *mp = m;
        }
    }
    __syncthreads();

    // ---- epilogue: all 128 threads, 2 pixels each ----
    const long long gpix = blockpix + tid * 2;

    float a2[10][2];
#pragma unroll
    for (int o = 0; o < 10; ++o) {
        const float2 m = *reinterpret_cast<const float2*>(&merge[o * PPB + tid * 2]);
        a2[o][0] = m.x; a2[o][1] = m.y;
    }

    const float inv_pi = 1.0f / PI_F;

    float wiL[6], woL[6];
    {
        const float2* wip2 = reinterpret_cast<const float2*>(wi + gpix * 3);
        const float2* wop2 = reinterpret_cast<const float2*>(wo + gpix * 3);
#pragma unroll
        for (int q = 0; q < 3; ++q) {
            float2 a  = __ldg(&wip2[q]);
            float2 bq = __ldg(&wop2[q]);
            wiL[q * 2 + 0] = a.x;  wiL[q * 2 + 1] = a.y;
            woL[q * 2 + 0] = bq.x; woL[q * 2 + 1] = bq.y;
        }
    }

    float img[6];

#pragma unroll
    for (int j = 0; j < 2; ++j) {
        const long long g = gpix + j;

        float nx = tanh_(a2[0][j]);
        float ny = tanh_(a2[1][j]);
        float nz = tanh_(a2[2][j]);
        {
            const float inv = rsq_(fmaxf(nx * nx + ny * ny + nz * nz, 1e-24f));
            nx *= inv; ny *= inv; nz *= inv;
        }
        const float al0 = sigmoid_(a2[3][j]);
        const float al1 = sigmoid_(a2[4][j]);
        const float al2 = sigmoid_(a2[5][j]);
        float rough = sigmoid_(a2[6][j]);
        rough = fminf(fmaxf(rough, 0.001f), 1.0f);
        const float f0x = sigmoid_(a2[7][j]);
        const float f0y = sigmoid_(a2[8][j]);
        const float f0z = sigmoid_(a2[9][j]);

        float lx = wiL[j * 3 + 0], ly = wiL[j * 3 + 1], lz = wiL[j * 3 + 2];
        float vx = woL[j * 3 + 0], vy = woL[j * 3 + 1], vz = woL[j * 3 + 2];
        {
            const float il = rsq_(fmaxf(lx * lx + ly * ly + lz * lz, 1e-24f));
            lx *= il; ly *= il; lz *= il;
        }
        {
            const float iv = rsq_(fmaxf(vx * vx + vy * vy + vz * vz, 1e-24f));
            vx *= iv; vy *= iv; vz *= iv;
        }
        float hx = lx + vx, hy = ly + vy, hz = lz + vz;
        {
            const float ih = rsq_(fmaxf(hx * hx + hy * hy + hz * hz, 1e-24f));
            hx *= ih; hy *= ih; hz *= ih;
        }

        const float NdotH = fmaxf(nx * hx + ny * hy + nz * hz, 1e-8f);
        const float NdotL = fmaxf(nx * lx + ny * ly + nz * lz, 1e-8f);
        const float NdotV = fmaxf(nx * vx + ny * vy + nz * vz, 1e-8f);
        const float VdotH = fmaxf(vx * hx + vy * hy + vz * hz, 1e-8f);

        const float alpha = rough * rough;
        const float a2g   = alpha * alpha;
        const float den   = fmaf(NdotH * NdotH, a2g - 1.0f, 1.0f);
        const float D     = a2g * rcp_(PI_F * den * den);
        const float Fe    = ex2_(fmaf(-5.55473f, VdotH, -6.98316f) * VdotH);
        const float k     = alpha * 0.5f;
        const float G     = rcp_(fmaf(NdotL, 1.0f - k, k)) *
                            rcp_(fmaf(NdotV, 1.0f - k, k));
        const float DG    = 0.25f * D * G;

        const float F0 = fmaf(1.0f - f0x, Fe, f0x);
        const float F1 = fmaf(1.0f - f0y, Fe, f0y);
        const float F2 = fmaf(1.0f - f0z, Fe, f0z);

        img[j * 3 + 0] = fmaxf((al0 * (1.0f - f0x) * inv_pi + DG * F0) * NdotL, 0.0f);
        img[j * 3 + 1] = fmaxf((al1 * (1.0f - f0y) * inv_pi + DG * F1) * NdotL, 0.0f);
        img[j * 3 + 2] = fmaxf((al2 * (1.0f - f0z) * inv_pi + DG * F2) * NdotL, 0.0f);

        float* dp = out_data + g * 12;
        stcs4_(dp + 0, nx,  ny,  nz,    al0);
        stcs4_(dp + 4, al1, al2, rough, rough);
        stcs4_(dp + 8, rough, f0x, f0y, f0z);
    }

    {
        float* ip = out_imgs + gpix * 3;
        stcs2_(ip + 0, img[0], img[1]);
        stcs2_(ip + 2, img[2], img[3]);
        stcs2_(ip + 4, img[4], img[5]);
    }
}

extern "C" void kernel_launch(void* const* d_in, const int* in_sizes, int n_in,
                              void* d_out, int out_size)
{
    const float* feats     = (const float*)d_in[0];
    const float* wi        = (const float*)d_in[1];
    const float* wo        = (const float*)d_in[2];
    const float* w_normal  = (const float*)d_in[3];
    const float* w_albedo  = (const float*)d_in[4];
    const float* w_rough   = (const float*)d_in[5];
    const float* w_fresnel = (const float*)d_in[6];

    float* out = (float*)d_out;
    const long long NPIX = (long long)BATCH * HW;   // 524288
    float* out_imgs = out;                           // [B,H,W,3]
    float* out_data = out + NPIX * 3;                // [B,H,W,12]

    const int blocks = (int)(NPIX / PPB);            // 2048
    brdf_fused_kernel<<<blocks, NTHR>>>(feats, wi, wo,
                                        w_normal, w_albedo, w_rough, w_fresnel,
                                        out_imgs, out_data);
}

// round 10
// speedup vs baseline: 1.8937x; 1.8937x over previous
#include <cuda_runtime.h>
#include <cstdint>

#define PI_F 3.14159265358979323846f
#define LOG2E_F 1.44269504088896340736f

constexpr int C_IN    = 256;
constexpr int HW      = 256 * 256;     // 65536
constexpr int BATCH   = 8;
constexpr int NTHR    = 128;
constexpr int HALF_T  = 64;            // threads per channel-half
constexpr int PPT     = 4;             // pixels per thread in the conv loop
constexpr int PPB     = HALF_T * PPT;  // 256 pixels per block
constexpr int CH_HALF = C_IN / 2;      // 128 channels per half
constexpr int RING_CH = 8;             // ring slots (channels) per half

// ---- fast math helpers (MUFU-based) ----
__device__ __forceinline__ float ex2_(float x) {
    float y; asm("ex2.approx.f32 %0, %1;" : "=f"(y) : "f"(x)); return y;
}
__device__ __forceinline__ float rcp_(float x) {
    float y; asm("rcp.approx.f32 %0, %1;" : "=f"(y) : "f"(x)); return y;
}
__device__ __forceinline__ float rsq_(float x) {
    float y; asm("rsqrt.approx.f32 %0, %1;" : "=f"(y) : "f"(x)); return y;
}
__device__ __forceinline__ float sigmoid_(float x) {
    return rcp_(1.0f + ex2_(-LOG2E_F * x));
}
__device__ __forceinline__ float tanh_(float x) {
    return 1.0f - 2.0f * rcp_(1.0f + ex2_(2.0f * LOG2E_F * x));
}

// ---- cp.async helpers (smem address as precomputed offset) ----
__device__ __forceinline__ void cpa16o_(unsigned saddr, const void* gsrc) {
    asm volatile("cp.async.cg.shared.global [%0], [%1], 16;\n"
                 :: "r"(saddr), "l"(gsrc) : "memory");
}
__device__ __forceinline__ void cpa_commit_() {
    asm volatile("cp.async.commit_group;\n" ::: "memory");
}
__device__ __forceinline__ void cpa_wait3_() {
    asm volatile("cp.async.wait_group 3;\n" ::: "memory");
}
__device__ __forceinline__ void cpa_wait2_() {
    asm volatile("cp.async.wait_group 2;\n" ::: "memory");
}
__device__ __forceinline__ void cpa_wait1_() {
    asm volatile("cp.async.wait_group 1;\n" ::: "memory");
}
__device__ __forceinline__ void cpa_wait0_() {
    asm volatile("cp.async.wait_group 0;\n" ::: "memory");
}

// ---- streaming stores (.cs: evict-first; outputs have no reuse) ----
__device__ __forceinline__ void stcs4_(float* p, float a, float b, float c, float d) {
    asm volatile("st.global.cs.v4.f32 [%0], {%1, %2, %3, %4};"
                 :: "l"(p), "f"(a), "f"(b), "f"(c), "f"(d) : "memory");
}
__device__ __forceinline__ void stcs2_(float* p, float a, float b) {
    asm volatile("st.global.cs.v2.f32 [%0], {%1, %2};"
                 :: "l"(p), "f"(a), "f"(b) : "memory");
}

// Consume one channel from ring slot SLOT (compile-time), weights pA/pB/pC[WIDX].
#define CONSUME_CH(SLOT, WIDX) do {                                          \
    const float4 f  = ringH[(SLOT) * HALF_T + lt];                           \
    const float4 wA = pA[WIDX];                                              \
    const float4 wB = pB[WIDX];                                              \
    const float2 wC = pC[WIDX];                                              \
    const float w[10] = {wA.x, wA.y, wA.z, wA.w, wB.x, wB.y, wB.z, wB.w,     \
                         wC.x, wC.y};                                        \
    const float fv[4] = {f.x, f.y, f.z, f.w};                                \
    _Pragma("unroll")                                                        \
    for (int o = 0; o < 10; ++o)                                             \
      _Pragma("unroll")                                                      \
      for (int j = 0; j < 4; ++j)                                            \
        acc[o][j] = fmaf(fv[j], w[o], acc[o][j]);                            \
  } while (0)

// Group body, 8-slot ring, DEPTH 4 (wait_group 3): at the wait, 3 groups
// (6 channels) remain in flight. SP = g%4. Consumes slots 2SP,2SP+1
// (channels WI,WI+1 of the current 8-channel macro block); then issues
// group g+4 (channels WI+8,WI+9) into the SAME two slots. Safe per thread:
// the LDS above issues before the async write below, and the write lands
// >= L2 latency later (validated in R9 — rel_err unchanged).
#define GROUP_BODY(SP, WI) {                                                 \
    cpa_wait3_();                                                            \
    CONSUME_CH(2 * (SP),     (WI));                                          \
    CONSUME_CH(2 * (SP) + 1, (WI) + 1);                                      \
    cpa16o_(rbase + (2 * (SP))     * (HALF_T * 16),                          \
            glp_m + (size_t)((WI) + 8) * HW);                                \
    cpa16o_(rbase + (2 * (SP) + 1) * (HALF_T * 16),                          \
            glp_m + (size_t)((WI) + 9) * HW);                                \
    cpa_commit_();                                                           \
  }

__global__ __launch_bounds__(NTHR, 8)
void brdf_fused_kernel(const float* __restrict__ feats,
                       const float* __restrict__ wi,
                       const float* __restrict__ wo,
                       const float* __restrict__ w_normal,
                       const float* __restrict__ w_albedo,
                       const float* __restrict__ w_rough,
                       const float* __restrict__ w_fresnel,
                       float* __restrict__ out_imgs,
                       float* __restrict__ out_data)
{
    // Weights in 3 aligned split arrays: 3 LDS broadcasts per channel. 10 KB.
    __shared__ float4 swA[C_IN];   // n0 n1 n2 a0
    __shared__ float4 swB[C_IN];   // a1 a2 r  f0
    __shared__ float2 swC[C_IN];   // f1 f2
    // Ring: 2 halves x 8 channel slots x 64 threads x 16 B = 16 KB.
    // After the loop it is reused as the 10x256-float merge buffer (10 KB).
    __shared__ __align__(16) float4 ringbuf[2 * RING_CH * HALF_T];

    const int tid = threadIdx.x;
    for (int i = tid; i < C_IN; i += NTHR) {
        swA[i] = make_float4(w_normal[0 * C_IN + i], w_normal[1 * C_IN + i],
                             w_normal[2 * C_IN + i], w_albedo[0 * C_IN + i]);
        swB[i] = make_float4(w_albedo[1 * C_IN + i], w_albedo[2 * C_IN + i],
                             w_rough[i],             w_fresnel[0 * C_IN + i]);
        swC[i] = make_float2(w_fresnel[1 * C_IN + i], w_fresnel[2 * C_IN + i]);
    }
    __syncthreads();

    const int h  = tid >> 6;        // channel-half: 0 or 1
    const int lt = tid & 63;        // lane within half

    const long long blockpix = (long long)blockIdx.x * PPB;
    const int b   = (int)(blockpix / HW);
    const int hwb = (int)(blockpix % HW);

    // This thread's 16B pixel slice in channel (h*128 + 0).
    const float* gl = feats + (size_t)b * C_IN * HW
                    + (size_t)(h * CH_HALF) * HW + hwb + lt * 4;

    float4* ringH = ringbuf + h * (RING_CH * HALF_T);
    const float4* pA = swA + h * CH_HALF;
    const float4* pB = swB + h * CH_HALF;
    const float2* pC = swC + h * CH_HALF;

    // Precomputed smem byte address of this thread's cell in slot 0.
    const unsigned rbase =
        (unsigned)__cvta_generic_to_shared(ringH) + (unsigned)(lt * 16);

    float acc[10][4];
#pragma unroll
    for (int o = 0; o < 10; ++o)
#pragma unroll
        for (int j = 0; j < 4; ++j) acc[o][j] = 0.f;

    // ---- prologue: groups 0..3 -> slots 0..7 (4 groups in flight) ----
    cpa16o_(rbase + 0 * (HALF_T * 16), gl);
    cpa16o_(rbase + 1 * (HALF_T * 16), gl + (size_t)HW);
    cpa_commit_();
    cpa16o_(rbase + 2 * (HALF_T * 16), gl + 2 * (size_t)HW);
    cpa16o_(rbase + 3 * (HALF_T * 16), gl + 3 * (size_t)HW);
    cpa_commit_();
    cpa16o_(rbase + 4 * (HALF_T * 16), gl + 4 * (size_t)HW);
    cpa16o_(rbase + 5 * (HALF_T * 16), gl + 5 * (size_t)HW);
    cpa_commit_();
    cpa16o_(rbase + 6 * (HALF_T * 16), gl + 6 * (size_t)HW);
    cpa16o_(rbase + 7 * (HALF_T * 16), gl + 7 * (size_t)HW);
    cpa_commit_();

    const float* glp_m = gl;   // base of current 8-channel macro block

    // ---- main loop: 15 macro-iterations x 4 groups = groups 0..59 ----
#pragma unroll 1
    for (int m = 0; m < 15; ++m) {
        GROUP_BODY(0, 0);      // consumes ch +0,+1, issues ch +8,+9
        GROUP_BODY(1, 2);      // consumes ch +2,+3, issues ch +10,+11
        GROUP_BODY(2, 4);      // consumes ch +4,+5, issues ch +12,+13
        GROUP_BODY(3, 6);      // consumes ch +6,+7, issues ch +14,+15
        pA += 8; pB += 8; pC += 8;
        glp_m += (size_t)8 * HW;
    }

    // ---- tail: groups 60..63 (local channels 120..127), no new issues ----
    cpa_wait3_();              // g=60 landed
    CONSUME_CH(0, 0);          // ch 120
    CONSUME_CH(1, 1);          // ch 121
    cpa_wait2_();              // g=61 landed
    CONSUME_CH(2, 2);          // ch 122
    CONSUME_CH(3, 3);          // ch 123
    cpa_wait1_();              // g=62 landed
    CONSUME_CH(4, 4);          // ch 124
    CONSUME_CH(5, 5);          // ch 125
    cpa_wait0_();              // g=63 landed; ring fully drained
    CONSUME_CH(6, 6);          // ch 126
    CONSUME_CH(7, 7);          // ch 127

    // ---- merge the two channel-halves through smem (ring is dead now) ----
    __syncthreads();

    float* merge = reinterpret_cast<float*>(ringbuf);   // [o][px]: 10 x 256
    if (h == 1) {
#pragma unroll
        for (int o = 0; o < 10; ++o)
            *reinterpret_cast<float4*>(&merge[o * PPB + lt * 4]) =
                make_float4(acc[o][0], acc[o][1], acc[o][2], acc[o][3]);
    }
    __syncthreads();
    if (h == 0) {
#pragma unroll
        for (int o = 0; o < 10; ++o) {
            float4* mp = reinterpret_cast<float4*>(&merge[o * PPB + lt * 4]);
            float4 m = *mp;
            m.x += acc[o][0]; m.y += acc[o][1];
            m.z += acc[o][2]; m.w += acc[o][3];
            *mp = m;
        }
    }
    __syncthreads();

    // ---- epilogue: all 128 threads, 2 pixels each ----
    const long long gpix = blockpix + tid * 2;

    float a2[10][2];
#pragma unroll
    for (int o = 0; o < 10; ++o) {
        const float2 m = *reinterpret_cast<const float2*>(&merge[o * PPB + tid * 2]);
        a2[o][0] = m.x; a2[o][1] = m.y;
    }

    const float inv_pi = 1.0f / PI_F;

    float wiL[6], woL[6];
    {
        const float2* wip2 = reinterpret_cast<const float2*>(wi + gpix * 3);
        const float2* wop2 = reinterpret_cast<const float2*>(wo + gpix * 3);
#pragma unroll
        for (int q = 0; q < 3; ++q) {
            float2 a  = __ldg(&wip2[q]);
            float2 bq = __ldg(&wop2[q]);
            wiL[q * 2 + 0] = a.x;  wiL[q * 2 + 1] = a.y;
            woL[q * 2 + 0] = bq.x; woL[q * 2 + 1] = bq.y;
        }
    }

    float img[6];

#pragma unroll
    for (int j = 0; j < 2; ++j) {
        const long long g = gpix + j;

        float nx = tanh_(a2[0][j]);
        float ny = tanh_(a2[1][j]);
        float nz = tanh_(a2[2][j]);
        {
            const float inv = rsq_(fmaxf(nx * nx + ny * ny + nz * nz, 1e-24f));
            nx *= inv; ny *= inv; nz *= inv;
        }
        const float al0 = sigmoid_(a2[3][j]);
        const float al1 = sigmoid_(a2[4][j]);
        const float al2 = sigmoid_(a2[5][j]);
        float rough = sigmoid_(a2[6][j]);
        rough = fminf(fmaxf(rough, 0.001f), 1.0f);
        const float f0x = sigmoid_(a2[7][j]);
        const float f0y = sigmoid_(a2[8][j]);
        const float f0z = sigmoid_(a2[9][j]);

        float lx = wiL[j * 3 + 0], ly = wiL[j * 3 + 1], lz = wiL[j * 3 + 2];
        float vx = woL[j * 3 + 0], vy = woL[j * 3 + 1], vz = woL[j * 3 + 2];
        {
            const float il = rsq_(fmaxf(lx * lx + ly * ly + lz * lz, 1e-24f));
            lx *= il; ly *= il; lz *= il;
        }
        {
            const float iv = rsq_(fmaxf(vx * vx + vy * vy + vz * vz, 1e-24f));
            vx *= iv; vy *= iv; vz *= iv;
        }
        float hx = lx + vx, hy = ly + vy, hz = lz + vz;
        {
            const float ih = rsq_(fmaxf(hx * hx + hy * hy + hz * hz, 1e-24f));
            hx *= ih; hy *= ih; hz *= ih;
        }

        const float NdotH = fmaxf(nx * hx + ny * hy + nz * hz, 1e-8f);
        const float NdotL = fmaxf(nx * lx + ny * ly + nz * lz, 1e-8f);
        const float NdotV = fmaxf(nx * vx + ny * vy + nz * vz, 1e-8f);
        const float VdotH = fmaxf(vx * hx + vy * hy + vz * hz, 1e-8f);

        const float alpha = rough * rough;
        const float a2g   = alpha * alpha;
        const float den   = fmaf(NdotH * NdotH, a2g - 1.0f, 1.0f);
        const float D     = a2g * rcp_(PI_F * den * den);
        const float Fe    = ex2_(fmaf(-5.55473f, VdotH, -6.98316f) * VdotH);
        const float k     = alpha * 0.5f;
        const float G     = rcp_(fmaf(NdotL, 1.0f - k, k)) *
                            rcp_(fmaf(NdotV, 1.0f - k, k));
        const float DG    = 0.25f * D * G;

        const float F0 = fmaf(1.0f - f0x, Fe, f0x);
        const float F1 = fmaf(1.0f - f0y, Fe, f0y);
        const float F2 = fmaf(1.0f - f0z, Fe, f0z);

        img[j * 3 + 0] = fmaxf((al0 * (1.0f - f0x) * inv_pi + DG * F0) * NdotL, 0.0f);
        img[j * 3 + 1] = fmaxf((al1 * (1.0f - f0y) * inv_pi + DG * F1) * NdotL, 0.0f);
        img[j * 3 + 2] = fmaxf((al2 * (1.0f - f0z) * inv_pi + DG * F2) * NdotL, 0.0f);

        float* dp = out_data + g * 12;
        stcs4_(dp + 0, nx,  ny,  nz,    al0);
        stcs4_(dp + 4, al1, al2, rough, rough);
        stcs4_(dp + 8, rough, f0x, f0y, f0z);
    }

    {
        float* ip = out_imgs + gpix * 3;
        stcs2_(ip + 0, img[0], img[1]);
        stcs2_(ip + 2, img[2], img[3]);
        stcs2_(ip + 4, img[4], img[5]);
    }
}

extern "C" void kernel_launch(void* const* d_in, const int* in_sizes, int n_in,
                              void* d_out, int out_size)
{
    const float* feats     = (const float*)d_in[0];
    const float* wi        = (const float*)d_in[1];
    const float* wo        = (const float*)d_in[2];
    const float* w_normal  = (const float*)d_in[3];
    const float* w_albedo  = (const float*)d_in[4];
    const float* w_rough   = (const float*)d_in[5];
    const float* w_fresnel = (const float*)d_in[6];

    float* out = (float*)d_out;
    const long long NPIX = (long long)BATCH * HW;   // 524288
    float* out_imgs = out;                           // [B,H,W,3]
    float* out_data = out + NPIX * 3;                // [B,H,W,12]

    const int blocks = (int)(NPIX / PPB);            // 2048
    brdf_fused_kernel<<<blocks, NTHR>>>(feats, wi, wo,
                                        w_normal, w_albedo, w_rough, w_fresnel,
                                        out_imgs, out_data);
}